// round 9
// baseline (speedup 1.0000x reference)
#include <cuda_runtime.h>
#include <cstdint>

typedef unsigned long long ull;

// ---------- packed f32x2 helpers ----------
__device__ __forceinline__ ull f2pack(float lo, float hi) {
    ull r; asm("mov.b64 %0,{%1,%2};" : "=l"(r) : "f"(lo), "f"(hi)); return r;
}
__device__ __forceinline__ void f2unpack(ull a, float& lo, float& hi) {
    asm("mov.b64 {%0,%1},%2;" : "=f"(lo), "=f"(hi) : "l"(a));
}
__device__ __forceinline__ ull f2mul(ull a, ull b) {
    ull r; asm("mul.rn.f32x2 %0,%1,%2;" : "=l"(r) : "l"(a), "l"(b)); return r;
}
__device__ __forceinline__ ull f2add(ull a, ull b) {
    ull r; asm("add.rn.f32x2 %0,%1,%2;" : "=l"(r) : "l"(a), "l"(b)); return r;
}
__device__ __forceinline__ ull f2fma(ull a, ull b, ull c) {
    ull r; asm("fma.rn.f32x2 %0,%1,%2,%3;" : "=l"(r) : "l"(a), "l"(b), "l"(c)); return r;
}

#define TW       64                 // tile width (pair cells)
#define TH       64                 // tile height (output rows); 512/64=8 -> no partial tiles
#define IN_W     74                 // TW + 10
#define TOT_R    74                 // TH + 10 input rows
#define CHUNK    15
#define NCH      5                  // 15,15,15,15,14
#define IN_PITCH 184                // ull per input row ({p,t} 16B cells, swizzled)
#define IN_ULL   (CHUNK * IN_PITCH)     // 2760
#define HB_PITCH 67                 // ull per hb row (8B cells, swizzled)
#define SIG_STRIDE (CHUNK * HB_PITCH)   // 1005
#define HB_ULL   (4 * SIG_STRIDE)       // 4020
#define NPIX     12582912.0         // 48 * 512 * 512
#define NBLOCKS  1536               // 8 x 8 x 24

// swizzles (conflict-free: h LDS.128 phases hit distinct quads, v/epi LDS.64 distinct mod 16)
__device__ __forceinline__ int in_off(int x) { return 2 * x + 2 * (x >> 2); }
__device__ __forceinline__ int c_off(int c)  { return c + (c >> 4); }

// symmetric window access: w[d] == w[10-d]
#define W(d) ws[(d) <= 5 ? (d) : 10 - (d)]

__device__ double        g_acc  = 0.0;
__device__ unsigned int  g_done = 0u;

// dynamic smem: inb[2760] | hb[4020] = 6780 ull = 54240 B -> 4 CTAs/SM (217 KB)
__global__ __launch_bounds__(256, 4) void ssim_main_k(
    const float* __restrict__ pred,
    const float* __restrict__ targ,
    const float* __restrict__ win,
    float* __restrict__ out)
{
    extern __shared__ ull sm[];
    ull* inb = sm;                  // interleaved {p,t} input chunk
    ull* hb  = sm + IN_ULL;         // h-blurred signals; overlaid output staging

    const int tid  = threadIdx.x;
    const int lane = tid & 31;
    const int warp = tid >> 5;

    // --- recover separable 1D window (symmetric): w1[j] = win[55+j]/rowsum ---
    float rowsum = 0.f;
#pragma unroll
    for (int j = 0; j < 11; j++) rowsum += __ldg(win + 55 + j);
    const float invr = 1.0f / rowsum;
    ull ws[6];
#pragma unroll
    for (int j = 0; j < 6; j++) {
        float w = __ldg(win + 55 + j) * invr;
        ws[j] = f2pack(w, w);
    }

    const int ox = blockIdx.x * TW;
    const int oy = blockIdx.y * TH;
    const int pz = blockIdx.z;                  // plane pair 0..23
    const float* p0 = pred + (size_t)pz * 524288;
    const float* p1 = p0 + 262144;
    const float* t0 = targ + (size_t)pz * 524288;
    const float* t1 = t0 + 262144;

    // identities
    const int hr  = tid >> 4;          // h-phase row in chunk (0..15)
    const int hx0 = (tid & 15) * 4;    // h-phase first output column
    const int vc  = tid & 63;          // v-phase column
    const int vs  = tid >> 6;          // v-phase signal

    const ull TWO  = f2pack(2.0f, 2.0f);
    const ull C1p  = f2pack(1e-4f, 1e-4f);
    const ull C2p  = f2pack(9e-4f, 9e-4f);
    const ull C12p = f2pack(1e-4f + 9e-4f, 1e-4f + 9e-4f);
    const ull EPSp = f2pack(1e-8f, 1e-8f);
    const ull SGN  = 0x8000000080000000ULL;

    // v sliding shift-register accumulators (persist across chunks)
    ull acc[11];
#pragma unroll
    for (int d = 0; d < 11; d++) acc[d] = 0ULL;

    float lsum = 0.f;

    // ---- initial load: chunk 0 ----
    for (int idx = tid; idx < CHUNK * IN_W; idx += 256) {
        int r = idx / IN_W, x = idx - r * IN_W;
        int gy = oy - 5 + r, gx = ox - 5 + x;
        float a0 = 0.f, a1 = 0.f, b0 = 0.f, b1 = 0.f;
        if (((unsigned)gy < 512u) && ((unsigned)gx < 512u)) {
            int g = gy * 512 + gx;
            a0 = __ldg(p0 + g); a1 = __ldg(p1 + g);
            b0 = __ldg(t0 + g); b1 = __ldg(t1 + g);
        }
        ull* cell = inb + r * IN_PITCH + in_off(x);
        cell[0] = f2pack(a0, a1);
        cell[1] = f2pack(b0, b1);
    }
    __syncthreads();

    for (int ch = 0; ch < NCH; ch++) {
        const int cs    = ch * CHUNK;
        const int nrows = (TOT_R - cs < CHUNK) ? (TOT_R - cs) : CHUNK;

        // ---- horizontal blur: thread = (row, 4-output x-group) ----
        if (hr < nrows) {
            const ull* rp = inb + hr * IN_PITCH;
            ull am1[4], am2[4], asq[4], apt[4];
#pragma unroll
            for (int j = 0; j < 4; j++) { am1[j]=0ULL; am2[j]=0ULL; asq[j]=0ULL; apt[j]=0ULL; }
#pragma unroll
            for (int k = 0; k < 14; k++) {
                ulonglong2 PT = *reinterpret_cast<const ulonglong2*>(rp + in_off(hx0 + k));
                ull p = PT.x, t = PT.y;
                ull sq = f2fma(p, p, f2mul(t, t));
                ull pt = f2mul(p, t);
#pragma unroll
                for (int j = 0; j < 4; j++) {
                    const int ki = k - j;
                    if (ki >= 0 && ki <= 10) {
                        ull w = W(ki);
                        am1[j] = f2fma(p,  w, am1[j]);
                        am2[j] = f2fma(t,  w, am2[j]);
                        asq[j] = f2fma(sq, w, asq[j]);
                        apt[j] = f2fma(pt, w, apt[j]);
                    }
                }
            }
#pragma unroll
            for (int j = 0; j < 4; j++) {
                int co = hr * HB_PITCH + c_off(hx0 + j);
                hb[0 * SIG_STRIDE + co] = am1[j];
                hb[1 * SIG_STRIDE + co] = am2[j];
                hb[2 * SIG_STRIDE + co] = asq[j];
                hb[3 * SIG_STRIDE + co] = apt[j];
            }
        }
        __syncthreads();

        // ---- vertical consume: shift-register; overlay completed rows into hb ----
        // Cell (vs, r, vc) is read+written ONLY by this thread -> overlay is race-free.
        {
            const ull* hs = hb + vs * SIG_STRIDE + c_off(vc);
            ull*       ss = const_cast<ull*>(hs);
#pragma unroll
            for (int r = 0; r < CHUNK; r++) {
                if (r < nrows) {
                    ull v = hs[r * HB_PITCH];
#pragma unroll
                    for (int d = 10; d >= 1; d--) acc[d] = f2fma(v, W(d), acc[d - 1]);
                    acc[0] = f2mul(v, W(0));
                    if (cs + r >= 10)
                        ss[r * HB_PITCH] = acc[10];   // slot = r (just-consumed row)
                }
            }
        }
        __syncthreads();

        // ---- fused phase: prefetch next chunk (regs) | epilogue | commit ----
        ull pf[5][2];
        const int cs2   = cs + CHUNK;
        const int nr2   = (ch < NCH - 1) ? ((TOT_R - cs2 < CHUNK) ? TOT_R - cs2 : CHUNK) : 0;
        const int ncell = nr2 * IN_W;
#pragma unroll
        for (int i = 0; i < 5; i++) {
            int idx = tid + i * 256;
            if (idx < ncell) {
                int r = idx / IN_W, x = idx - r * IN_W;
                int gy = oy - 5 + cs2 + r, gx = ox - 5 + x;
                float a0 = 0.f, a1 = 0.f, b0 = 0.f, b1 = 0.f;
                if (((unsigned)gy < 512u) && ((unsigned)gx < 512u)) {
                    int g = gy * 512 + gx;
                    a0 = __ldg(p0 + g); a1 = __ldg(p1 + g);
                    b0 = __ldg(t0 + g); b1 = __ldg(t1 + g);
                }
                pf[i][0] = f2pack(a0, a1);
                pf[i][1] = f2pack(b0, b1);
            }
        }

        // epilogue: outputs e in [max(0,cs-10), cs+nrows-10), slot = e-cs+10
        {
            const int e0 = (cs >= 10) ? cs - 10 : 0;
            const int e1 = cs + nrows - 10;
            const int ntask = (e1 - e0) * TW;
            for (int t2 = tid; t2 < ntask; t2 += 256) {
                int e = e0 + (t2 >> 6);
                int c = t2 & 63;
                int base = (e - cs + 10) * HB_PITCH + c_off(c);
                ull bm1 = hb[0 * SIG_STRIDE + base];
                ull bm2 = hb[1 * SIG_STRIDE + base];
                ull bsq = hb[2 * SIG_STRIDE + base];
                ull bpt = hb[3 * SIG_STRIDE + base];
                ull m12   = f2mul(bm1, bm2);
                ull den1  = f2fma(bm1, bm1, f2fma(bm2, bm2, C1p));   // mu1^2+mu2^2+C1
                ull den2  = f2add(f2add(bsq, C12p), den1 ^ SGN);     // bsq - den1 + C1+C2
                ull sig12 = f2add(bpt, m12 ^ SGN);                   // bpt - m12
                ull num1  = f2fma(m12,   TWO, C1p);
                ull num2  = f2fma(sig12, TWO, C2p);
                ull num   = f2mul(num1, num2);
                ull den   = f2fma(den1, den2, EPSp);
                float n0, n1, d0, d1;
                f2unpack(num, n0, n1);
                f2unpack(den, d0, d1);
                lsum += __fdividef(n0, d0) + __fdividef(n1, d1);
            }
        }

        // commit prefetched inputs
#pragma unroll
        for (int i = 0; i < 5; i++) {
            int idx = tid + i * 256;
            if (idx < ncell) {
                int r = idx / IN_W, x = idx - r * IN_W;
                ull* cell = inb + r * IN_PITCH + in_off(x);
                cell[0] = pf[i][0];
                cell[1] = pf[i][1];
            }
        }
        __syncthreads();
    }

    // --- block reduction -> double atomic + last-block finalize ---
#pragma unroll
    for (int o = 16; o; o >>= 1) lsum += __shfl_xor_sync(0xffffffffu, lsum, o);
    __shared__ float warp_part[8];
    if (lane == 0) warp_part[warp] = lsum;
    __syncthreads();
    if (tid == 0) {
        float v = 0.f;
#pragma unroll
        for (int i = 0; i < 8; i++) v += warp_part[i];
        atomicAdd(&g_acc, (double)v);
        __threadfence();
        unsigned int old = atomicAdd(&g_done, 1u);
        if (old == NBLOCKS - 1u) {
            __threadfence();
            double total = *((volatile double*)&g_acc);
            out[0] = 1.0f - (float)(total * (1.0 / NPIX));
            g_acc  = 0.0;
            g_done = 0u;
        }
    }
}

extern "C" void kernel_launch(void* const* d_in, const int* in_sizes, int n_in,
                              void* d_out, int out_size)
{
    const float* pred = (const float*)d_in[0];
    const float* targ = (const float*)d_in[1];
    const float* win  = (const float*)d_in[2];
    float* out = (float*)d_out;

    const int smem_bytes = (IN_ULL + HB_ULL) * 8;   // 54240
    cudaFuncSetAttribute(ssim_main_k, cudaFuncAttributeMaxDynamicSharedMemorySize, smem_bytes);

    dim3 grid(8, 8, 24), blk(256);
    ssim_main_k<<<grid, blk, smem_bytes>>>(pred, targ, win, out);
}

// round 10
// speedup vs baseline: 1.1652x; 1.1652x over previous
#include <cuda_runtime.h>
#include <cstdint>

typedef unsigned long long ull;

// ---------- packed f32x2 helpers ----------
__device__ __forceinline__ ull f2pack(float lo, float hi) {
    ull r; asm("mov.b64 %0,{%1,%2};" : "=l"(r) : "f"(lo), "f"(hi)); return r;
}
__device__ __forceinline__ void f2unpack(ull a, float& lo, float& hi) {
    asm("mov.b64 {%0,%1},%2;" : "=f"(lo), "=f"(hi) : "l"(a));
}
__device__ __forceinline__ ull f2mul(ull a, ull b) {
    ull r; asm("mul.rn.f32x2 %0,%1,%2;" : "=l"(r) : "l"(a), "l"(b)); return r;
}
__device__ __forceinline__ ull f2add(ull a, ull b) {
    ull r; asm("add.rn.f32x2 %0,%1,%2;" : "=l"(r) : "l"(a), "l"(b)); return r;
}
__device__ __forceinline__ ull f2fma(ull a, ull b, ull c) {
    ull r; asm("fma.rn.f32x2 %0,%1,%2,%3;" : "=l"(r) : "l"(a), "l"(b), "l"(c)); return r;
}

#define TW       64                 // tile width (pair cells); 512/64=8 -> no partial x tiles
#define TH       64                 // tile height (output rows)
#define IN_W     74                 // TW + 10
#define TOT_R    74                 // TH + 10 input rows
#define CHUNK    15
#define NCH      5                  // 15,15,15,15,14
#define IN_PITCH 184                // ull per input row ({p,t} 16B cells, swizzled)
#define IN_ULL   (CHUNK * IN_PITCH)     // 2760
#define HB_PITCH 67                 // ull per hb row (8B cells, swizzled)
#define SIG_STRIDE (CHUNK * HB_PITCH)   // 1005
#define HB_ULL   (4 * SIG_STRIDE)       // 4020
#define NPIX     12582912.0         // 48 * 512 * 512
#define NBLOCKS  1536               // 8 x 8 x 24

// swizzles (conflict-free: h LDS.128 phases hit distinct quads, v/epi LDS.64 distinct mod 16)
__device__ __forceinline__ int in_off(int x) { return 2 * x + 2 * (x >> 2); }
__device__ __forceinline__ int c_off(int c)  { return c + (c >> 4); }

// symmetric window access: w[d] == w[10-d] (bit-exact on the recovered 1D window)
#define W(d) ws[(d) <= 5 ? (d) : 10 - (d)]

__device__ double        g_acc  = 0.0;
__device__ unsigned int  g_done = 0u;

// dynamic smem: inb[2760] | hb[4020] = 6780 ull = 54240 B -> 4 CTAs/SM (217 KB)
__global__ __launch_bounds__(256, 4) void ssim_main_k(
    const float* __restrict__ pred,
    const float* __restrict__ targ,
    const float* __restrict__ win,
    float* __restrict__ out)
{
    extern __shared__ ull sm[];
    ull* inb = sm;                  // interleaved {p,t} input chunk
    ull* hb  = sm + IN_ULL;         // h-blurred signals; overlaid output staging

    const int tid  = threadIdx.x;
    const int lane = tid & 31;
    const int warp = tid >> 5;

    // --- recover separable 1D window (symmetric): w1[j] = win[55+j]/rowsum ---
    float rowsum = 0.f;
#pragma unroll
    for (int j = 0; j < 11; j++) rowsum += __ldg(win + 55 + j);
    const float invr = 1.0f / rowsum;
    ull ws[6];
#pragma unroll
    for (int j = 0; j < 6; j++) {
        float w = __ldg(win + 55 + j) * invr;
        ws[j] = f2pack(w, w);
    }

    const int ox = blockIdx.x * TW;
    const int oy = blockIdx.y * TH;
    const int pz = blockIdx.z;                  // plane pair 0..23
    const float* p0 = pred + (size_t)pz * 524288;
    const float* p1 = p0 + 262144;
    const float* t0 = targ + (size_t)pz * 524288;
    const float* t1 = t0 + 262144;

    // identities
    const int hr  = tid >> 4;          // h-phase row in chunk (0..15)
    const int hx0 = (tid & 15) * 4;    // h-phase first output column
    const int vc  = tid & 63;          // v-phase column
    const int vs  = tid >> 6;          // v-phase signal

    const ull TWO  = f2pack(2.0f, 2.0f);
    const ull C1p  = f2pack(1e-4f, 1e-4f);
    const ull C2p  = f2pack(9e-4f, 9e-4f);
    const ull C12p = f2pack(1e-4f + 9e-4f, 1e-4f + 9e-4f);
    const ull EPSp = f2pack(1e-8f, 1e-8f);
    const ull SGN  = 0x8000000080000000ULL;

    // v sliding shift-register accumulators (persist across chunks)
    ull acc[11];
#pragma unroll
    for (int d = 0; d < 11; d++) acc[d] = 0ULL;

    float lsum = 0.f;

    // ---- initial load: chunk 0 (direct to smem) ----
    for (int idx = tid; idx < CHUNK * IN_W; idx += 256) {
        int r = idx / IN_W, x = idx - r * IN_W;
        int gy = oy - 5 + r, gx = ox - 5 + x;
        float a0 = 0.f, a1 = 0.f, b0 = 0.f, b1 = 0.f;
        if (((unsigned)gy < 512u) && ((unsigned)gx < 512u)) {
            int g = gy * 512 + gx;
            a0 = __ldg(p0 + g); a1 = __ldg(p1 + g);
            b0 = __ldg(t0 + g); b1 = __ldg(t1 + g);
        }
        ull* cell = inb + r * IN_PITCH + in_off(x);
        cell[0] = f2pack(a0, a1);
        cell[1] = f2pack(b0, b1);
    }
    __syncthreads();

    for (int ch = 0; ch < NCH; ch++) {
        const int cs    = ch * CHUNK;
        const int nrows = (TOT_R - cs < CHUNK) ? (TOT_R - cs) : CHUNK;

        // ---- horizontal blur: thread = (row, 4-output x-group) ----
        if (hr < nrows) {
            const ull* rp = inb + hr * IN_PITCH;
            ull am1[4], am2[4], asq[4], apt[4];
#pragma unroll
            for (int j = 0; j < 4; j++) { am1[j]=0ULL; am2[j]=0ULL; asq[j]=0ULL; apt[j]=0ULL; }
#pragma unroll
            for (int k = 0; k < 14; k++) {
                ulonglong2 PT = *reinterpret_cast<const ulonglong2*>(rp + in_off(hx0 + k));
                ull p = PT.x, t = PT.y;
                ull sq = f2fma(p, p, f2mul(t, t));
                ull pt = f2mul(p, t);
#pragma unroll
                for (int j = 0; j < 4; j++) {
                    const int ki = k - j;
                    if (ki >= 0 && ki <= 10) {
                        ull w = W(ki);
                        am1[j] = f2fma(p,  w, am1[j]);
                        am2[j] = f2fma(t,  w, am2[j]);
                        asq[j] = f2fma(sq, w, asq[j]);
                        apt[j] = f2fma(pt, w, apt[j]);
                    }
                }
            }
#pragma unroll
            for (int j = 0; j < 4; j++) {
                int co = hr * HB_PITCH + c_off(hx0 + j);
                hb[0 * SIG_STRIDE + co] = am1[j];
                hb[1 * SIG_STRIDE + co] = am2[j];
                hb[2 * SIG_STRIDE + co] = asq[j];
                hb[3 * SIG_STRIDE + co] = apt[j];
            }
        }
        __syncthreads();

        // ---- vertical consume: shift-register; overlay completed rows into hb ----
        // Cell (vs, r, vc) is read+written ONLY by this thread -> overlay is race-free.
        {
            ull* hs = hb + vs * SIG_STRIDE + c_off(vc);
#pragma unroll
            for (int r = 0; r < CHUNK; r++) {
                if (r < nrows) {
                    ull v = hs[r * HB_PITCH];
#pragma unroll
                    for (int d = 10; d >= 1; d--) acc[d] = f2fma(v, W(d), acc[d - 1]);
                    acc[0] = f2mul(v, W(0));
                    if (cs + r >= 10)
                        hs[r * HB_PITCH] = acc[10];   // slot = r (just-consumed row)
                }
            }
        }
        __syncthreads();

        // ---- fused phase: epilogue (reads hb overlay) + load next chunk (writes inb) ----
        {
            const int e0 = (cs >= 10) ? cs - 10 : 0;
            const int e1 = cs + nrows - 10;
            const int ntask = (e1 - e0) * TW;
            for (int t2 = tid; t2 < ntask; t2 += 256) {
                int e = e0 + (t2 >> 6);
                int c = t2 & 63;
                int base = (e - cs + 10) * HB_PITCH + c_off(c);
                ull bm1 = hb[0 * SIG_STRIDE + base];
                ull bm2 = hb[1 * SIG_STRIDE + base];
                ull bsq = hb[2 * SIG_STRIDE + base];
                ull bpt = hb[3 * SIG_STRIDE + base];
                ull m12   = f2mul(bm1, bm2);
                ull den1  = f2fma(bm1, bm1, f2fma(bm2, bm2, C1p));   // mu1^2+mu2^2+C1
                ull den2  = f2add(f2add(bsq, C12p), den1 ^ SGN);     // bsq - den1 + C1+C2
                ull sig12 = f2add(bpt, m12 ^ SGN);                   // bpt - m12
                ull num1  = f2fma(m12,   TWO, C1p);
                ull num2  = f2fma(sig12, TWO, C2p);
                ull num   = f2mul(num1, num2);
                ull den   = f2fma(den1, den2, EPSp);
                float n0, n1, d0, d1;
                f2unpack(num, n0, n1);
                f2unpack(den, d0, d1);
                lsum += __fdividef(n0, d0) + __fdividef(n1, d1);
            }
        }

        // load chunk ch+1 directly into inb (h-phase for chunk ch is done)
        if (ch < NCH - 1) {
            const int cs2 = cs + CHUNK;
            const int nr2 = (TOT_R - cs2 < CHUNK) ? (TOT_R - cs2) : CHUNK;
            for (int idx = tid; idx < nr2 * IN_W; idx += 256) {
                int r = idx / IN_W, x = idx - r * IN_W;
                int gy = oy - 5 + cs2 + r, gx = ox - 5 + x;
                float a0 = 0.f, a1 = 0.f, b0 = 0.f, b1 = 0.f;
                if (((unsigned)gy < 512u) && ((unsigned)gx < 512u)) {
                    int g = gy * 512 + gx;
                    a0 = __ldg(p0 + g); a1 = __ldg(p1 + g);
                    b0 = __ldg(t0 + g); b1 = __ldg(t1 + g);
                }
                ull* cell = inb + r * IN_PITCH + in_off(x);
                cell[0] = f2pack(a0, a1);
                cell[1] = f2pack(b0, b1);
            }
        }
        __syncthreads();
    }

    // --- block reduction -> double atomic + last-block finalize ---
#pragma unroll
    for (int o = 16; o; o >>= 1) lsum += __shfl_xor_sync(0xffffffffu, lsum, o);
    __shared__ float warp_part[8];
    if (lane == 0) warp_part[warp] = lsum;
    __syncthreads();
    if (tid == 0) {
        float v = 0.f;
#pragma unroll
        for (int i = 0; i < 8; i++) v += warp_part[i];
        atomicAdd(&g_acc, (double)v);
        __threadfence();
        unsigned int old = atomicAdd(&g_done, 1u);
        if (old == NBLOCKS - 1u) {
            __threadfence();
            double total = *((volatile double*)&g_acc);
            out[0] = 1.0f - (float)(total * (1.0 / NPIX));
            g_acc  = 0.0;
            g_done = 0u;
        }
    }
}

extern "C" void kernel_launch(void* const* d_in, const int* in_sizes, int n_in,
                              void* d_out, int out_size)
{
    const float* pred = (const float*)d_in[0];
    const float* targ = (const float*)d_in[1];
    const float* win  = (const float*)d_in[2];
    float* out = (float*)d_out;

    const int smem_bytes = (IN_ULL + HB_ULL) * 8;   // 54240
    cudaFuncSetAttribute(ssim_main_k, cudaFuncAttributeMaxDynamicSharedMemorySize, smem_bytes);

    dim3 grid(8, 8, 24), blk(256);
    ssim_main_k<<<grid, blk, smem_bytes>>>(pred, targ, win, out);
}